// round 9
// baseline (speedup 1.0000x reference)
#include <cuda_runtime.h>
#include <cuda_fp16.h>
#include <cstdint>

#define TB      256
#define GRID    148
#define HID     128
#define TSTEPS  28
#define XROW    784
#define NTASKS  4096         // 65536 / 16 rows per warp-task
#define NWARPS  (GRID * 8)
#define WSTR    168          // W row stride in halves (336 B, conflict-free ldsm)
#define SMEM_TOTAL (512 * WSTR * 2)   // 172032 B, W only

__device__ __forceinline__ uint32_t su32(const void* p) {
    uint32_t a;
    asm("{ .reg .u64 t; cvta.to.shared.u64 t, %1; cvt.u32.u64 %0, t; }" : "=r"(a) : "l"(p));
    return a;
}

// NOTE: non-volatile, no memory clobber — pure register ops on read-only smem.
// Lets NVVM/ptxas interleave loads and MMAs across chunk boundaries.
#define LDSM4(R0, R1, R2, R3, ADDR)                                            \
    asm("ldmatrix.sync.aligned.m8n8.x4.shared.b16 {%0,%1,%2,%3}, [%4];"         \
        : "=r"(R0), "=r"(R1), "=r"(R2), "=r"(R3) : "r"(ADDR))

#define MMA(D, A0, A1, A2, A3, B0, B1)                                         \
    asm("mma.sync.aligned.m16n8k16.row.col.f32.f16.f16.f32 "                   \
        "{%0,%1,%2,%3}, {%4,%5,%6,%7}, {%8,%9}, {%0,%1,%2,%3};"                \
        : "+f"((D)[0]), "+f"((D)[1]), "+f"((D)[2]), "+f"((D)[3])               \
        : "r"(A0), "r"(A1), "r"(A2), "r"(A3), "r"(B0), "r"(B1))

__device__ __forceinline__ float ftanh(float v) {
    float r;
    asm("tanh.approx.f32 %0, %1;" : "=f"(r) : "f"(v));
    return r;
}
__device__ __forceinline__ float fsig(float v) {
    return fmaf(0.5f, ftanh(0.5f * v), 0.5f);
}
// pack two fp32 -> fp16x2 register: lo = a, hi = b
__device__ __forceinline__ uint32_t h2u(float a, float b) {
    uint32_t u;
    asm("cvt.rn.f16x2.f32 %0, %1, %2;" : "=r"(u) : "f"(b), "f"(a));
    return u;
}
__device__ __forceinline__ uint32_t f2u(float2 v) { return h2u(v.x, v.y); }

__global__ void __launch_bounds__(TB, 1)
lstm_kernel(const float* __restrict__ x,
            const float* __restrict__ Wf, const float* __restrict__ bf_,
            const float* __restrict__ Wi, const float* __restrict__ bi_,
            const float* __restrict__ Wc, const float* __restrict__ bc_,
            const float* __restrict__ Wo, const float* __restrict__ bo_,
            float* __restrict__ out)
{
    extern __shared__ char smem[];
    const uint32_t sbase = su32(smem);
    half* const Wh = (half*)smem;

    const int tid  = threadIdx.x;
    const int lane = tid & 31, wid = tid >> 5;

    // ---- one-time init: W (K-major, gate-major rows, bias col @156, pads 0) ----
    {
        uint32_t* zw = (uint32_t*)smem;
        for (int i = tid; i < 512 * WSTR / 2; i += TB) zw[i] = 0u;
    }
    __syncthreads();
    for (int idx = tid; idx < 4 * 128 * 156; idx += TB) {
        int g = idx / 19968;
        int rem = idx - g * 19968;
        int hrow = rem / 156;
        int k = rem - hrow * 156;
        const float* Wg = (g == 0) ? Wf : (g == 1) ? Wi : (g == 2) ? Wc : Wo;
        Wh[((g << 7) + hrow) * WSTR + k] = __float2half(Wg[rem]);
    }
    for (int n = tid; n < 512; n += TB) {
        int g = n >> 7, j = n & 127;
        const float* bp = (g == 0) ? bf_ : (g == 1) ? bi_ : (g == 2) ? bc_ : bo_;
        Wh[n * WSTR + 156] = __float2half(bp[j]);
    }
    __syncthreads();

    // ---- per-thread constants ----
    const int rlo = lane >> 2;            // row within 16-row strip (low); +8 = high
    const int c0  = (lane & 3) * 2;       // frag column offset
    const uint32_t bbase = sbase
        + (uint32_t)((lane & 7) + ((lane >> 4) << 3)) * (WSTR * 2)
        + (uint32_t)(((lane >> 3) & 1) * 8) * 2;
    const int xdmode = (c0 < 4) ? 0 : ((c0 == 4) ? 1 : 2);
    const uint32_t XBIAS = h2u(1.0f, 0.0f);

    // tail-spread ordering: 4th-phase warps (o < 544) are wid 0-3 across ALL SMs
    const int o = wid * GRID + blockIdx.x;

    // ================= per-warp independent recurrences =================
    #pragma unroll 1
    for (int task = o; task < NTASKS; task += NWARPS) {
        const size_t growlo = (size_t)task * 16 + rlo;
        const float* xlo = x + growlo * XROW;
        const float* xhi = xlo + (size_t)8 * XROW;

        uint32_t hA[8][4];                 // h_t as ready-made A fragments (fp16x2)
        #pragma unroll
        for (int i = 0; i < 8; i++)
            #pragma unroll
            for (int r = 0; r < 4; r++) hA[i][r] = 0u;
        float cst[64];
        #pragma unroll
        for (int i = 0; i < 64; i++) cst[i] = 0.0f;

        // prefetch x for t=0
        float2 pa_lo = *(const float2*)(xlo + c0);
        float2 pa_hi = *(const float2*)(xhi + c0);
        float2 pb_lo = *(const float2*)(xlo + c0 + 8);
        float2 pb_hi = *(const float2*)(xhi + c0 + 8);
        float2 pc_lo = *(const float2*)(xlo + 16 + c0);
        float2 pc_hi = *(const float2*)(xhi + 16 + c0);
        float2 pd_lo = (xdmode == 0) ? *(const float2*)(xlo + 24 + c0) : make_float2(0, 0);
        float2 pd_hi = (xdmode == 0) ? *(const float2*)(xhi + 24 + c0) : make_float2(0, 0);

        #pragma unroll 1
        for (int t = 0; t < TSTEPS; t++) {
            const bool last = (t == TSTEPS - 1);

            // pack x A-fragments for this step
            uint32_t xf8[4], xf9[4];
            xf8[0] = f2u(pa_lo); xf8[1] = f2u(pa_hi);
            xf8[2] = f2u(pb_lo); xf8[3] = f2u(pb_hi);
            xf9[0] = f2u(pc_lo); xf9[1] = f2u(pc_hi);
            xf9[2] = (xdmode == 0) ? f2u(pd_lo) : ((xdmode == 1) ? XBIAS : 0u);
            xf9[3] = (xdmode == 0) ? f2u(pd_hi) : ((xdmode == 1) ? XBIAS : 0u);

            // prefetch x for t+1 (covers full MMA+epilogue latency)
            if (!last) {
                const float* ql = xlo + (size_t)(t + 1) * 28;
                const float* qh = xhi + (size_t)(t + 1) * 28;
                pa_lo = *(const float2*)(ql + c0);      pa_hi = *(const float2*)(qh + c0);
                pb_lo = *(const float2*)(ql + c0 + 8);  pb_hi = *(const float2*)(qh + c0 + 8);
                pc_lo = *(const float2*)(ql + 16 + c0); pc_hi = *(const float2*)(qh + 16 + c0);
                if (xdmode == 0) {
                    pd_lo = *(const float2*)(ql + 24 + c0);
                    pd_hi = *(const float2*)(qh + 24 + c0);
                }
            }

            uint32_t hN[8][4];

            #pragma unroll
            for (int ch = 0; ch < 8; ch++) {
                float acc[4][2][4];        // [gate][n8][reg]
                #pragma unroll
                for (int g = 0; g < 4; g++)
                    #pragma unroll
                    for (int n8 = 0; n8 < 2; n8++)
                        #pragma unroll
                        for (int r = 0; r < 4; r++) acc[g][n8][r] = 0.0f;

                #pragma unroll
                for (int ks = 0; ks < 10; ks++) {
                    const uint32_t* A = (ks < 8) ? hA[ks] : ((ks == 8) ? xf8 : xf9);
                    #pragma unroll
                    for (int g = 0; g < 4; g++) {
                        uint32_t b0, b1, b2, b3;
                        LDSM4(b0, b1, b2, b3,
                              bbase + (uint32_t)(((g << 7) + (ch << 4)) * (WSTR * 2)
                                                 + ks * 32));
                        MMA(acc[g][0], A[0], A[1], A[2], A[3], b0, b1);
                        MMA(acc[g][1], A[0], A[1], A[2], A[3], b2, b3);
                    }
                }

                // epilogue: 16 hidden units of this chunk (j = ch*16 + n8*8 + c0 + jc)
                #pragma unroll
                for (int n8 = 0; n8 < 2; n8++) {
                    #pragma unroll
                    for (int mi = 0; mi < 2; mi++) {
                        float hv0, hv1;
                        #pragma unroll
                        for (int jc = 0; jc < 2; jc++) {
                            const int ai = mi * 2 + jc;
                            float fs = fsig(acc[0][n8][ai]);
                            float is = fsig(acc[1][n8][ai]);
                            float ns = ftanh(acc[2][n8][ai]);
                            float os = fsig(acc[3][n8][ai]);
                            const int ci = (ch << 3) + (n8 << 2) + (mi << 1) + jc;
                            float cc = fmaf(cst[ci], fs, is * ns);
                            cst[ci] = cc;
                            float hh = os * ftanh(cc);
                            if (jc == 0) hv0 = hh; else hv1 = hh;
                        }
                        if (last) {
                            const int j = (ch << 4) + (n8 << 3) + c0;
                            *(float2*)(out + (growlo + mi * 8) * HID + j) =
                                make_float2(hv0, hv1);
                        } else {
                            hN[ch][(n8 << 1) + mi] = h2u(hv0, hv1);
                        }
                    }
                }
            }

            if (!last) {
                #pragma unroll
                for (int i = 0; i < 8; i++)
                    #pragma unroll
                    for (int r = 0; r < 4; r++) hA[i][r] = hN[i][r];
            }
        }
    }
}

extern "C" void kernel_launch(void* const* d_in, const int* in_sizes, int n_in,
                              void* d_out, int out_size) {
    (void)in_sizes; (void)n_in; (void)out_size;
    cudaFuncSetAttribute(lstm_kernel, cudaFuncAttributeMaxDynamicSharedMemorySize,
                         SMEM_TOTAL);
    lstm_kernel<<<GRID, TB, SMEM_TOTAL>>>(
        (const float*)d_in[0],
        (const float*)d_in[1], (const float*)d_in[2],
        (const float*)d_in[3], (const float*)d_in[4],
        (const float*)d_in[5], (const float*)d_in[6],
        (const float*)d_in[7], (const float*)d_in[8],
        (float*)d_out);
}

// round 10
// speedup vs baseline: 1.2175x; 1.2175x over previous
#include <cuda_runtime.h>
#include <cuda_fp16.h>
#include <cstdint>

#define TB      256
#define GRID    148
#define HID     128
#define TSTEPS  28
#define XROW    784
#define NTASKS  4096         // 65536 / 16 rows per warp-task
#define NWARPS  (GRID * 8)
#define WSTR    168          // W row stride in halves (336 B, conflict-free ldsm)
#define SMEM_TOTAL (512 * WSTR * 2)   // 172032 B, W only

__device__ __forceinline__ uint32_t su32(const void* p) {
    uint32_t a;
    asm("{ .reg .u64 t; cvta.to.shared.u64 t, %1; cvt.u32.u64 %0, t; }" : "=r"(a) : "l"(p));
    return a;
}

#define LDSM4(R0, R1, R2, R3, ADDR)                                            \
    asm volatile("ldmatrix.sync.aligned.m8n8.x4.shared.b16 {%0,%1,%2,%3}, [%4];" \
                 : "=r"(R0), "=r"(R1), "=r"(R2), "=r"(R3) : "r"(ADDR))

#define MMA(D, A0, A1, A2, A3, B0, B1)                                         \
    asm volatile("mma.sync.aligned.m16n8k16.row.col.f32.f16.f16.f32 "          \
                 "{%0,%1,%2,%3}, {%4,%5,%6,%7}, {%8,%9}, {%0,%1,%2,%3};"       \
                 : "+f"((D)[0]), "+f"((D)[1]), "+f"((D)[2]), "+f"((D)[3])      \
                 : "r"(A0), "r"(A1), "r"(A2), "r"(A3), "r"(B0), "r"(B1))

__device__ __forceinline__ float ftanh(float v) {
    float r;
    asm("tanh.approx.f32 %0, %1;" : "=f"(r) : "f"(v));
    return r;
}
__device__ __forceinline__ float fsig(float v) {
    return fmaf(0.5f, ftanh(0.5f * v), 0.5f);
}
// pack two fp32 -> fp16x2 register: lo = a, hi = b
__device__ __forceinline__ uint32_t h2u(float a, float b) {
    uint32_t u;
    asm("cvt.rn.f16x2.f32 %0, %1, %2;" : "=r"(u) : "f"(b), "f"(a));
    return u;
}
__device__ __forceinline__ uint32_t f2u(float2 v) { return h2u(v.x, v.y); }

__global__ void __launch_bounds__(TB, 1)
lstm_kernel(const float* __restrict__ x,
            const float* __restrict__ Wf, const float* __restrict__ bf_,
            const float* __restrict__ Wi, const float* __restrict__ bi_,
            const float* __restrict__ Wc, const float* __restrict__ bc_,
            const float* __restrict__ Wo, const float* __restrict__ bo_,
            float* __restrict__ out)
{
    extern __shared__ char smem[];
    const uint32_t sbase = su32(smem);
    half* const Wh = (half*)smem;

    const int tid  = threadIdx.x;
    const int lane = tid & 31, wid = tid >> 5;

    // ---- one-time init: W (K-major, gate-major rows, bias col @156, pads 0) ----
    {
        uint32_t* zw = (uint32_t*)smem;
        for (int i = tid; i < 512 * WSTR / 2; i += TB) zw[i] = 0u;
    }
    __syncthreads();
    for (int idx = tid; idx < 4 * 128 * 156; idx += TB) {
        int g = idx / 19968;
        int rem = idx - g * 19968;
        int hrow = rem / 156;
        int k = rem - hrow * 156;
        const float* Wg = (g == 0) ? Wf : (g == 1) ? Wi : (g == 2) ? Wc : Wo;
        Wh[((g << 7) + hrow) * WSTR + k] = __float2half(Wg[rem]);
    }
    for (int n = tid; n < 512; n += TB) {
        int g = n >> 7, j = n & 127;
        const float* bp = (g == 0) ? bf_ : (g == 1) ? bi_ : (g == 2) ? bc_ : bo_;
        Wh[n * WSTR + 156] = __float2half(bp[j]);
    }
    __syncthreads();

    // ---- per-thread constants ----
    const int rlo = lane >> 2;            // row within 16-row strip (low); +8 = high
    const int c0  = (lane & 3) * 2;       // frag column offset
    const uint32_t bbase = sbase
        + (uint32_t)((lane & 7) + ((lane >> 4) << 3)) * (WSTR * 2)
        + (uint32_t)(((lane >> 3) & 1) * 8) * 2;
    const int xdmode = (c0 < 4) ? 0 : ((c0 == 4) ? 1 : 2);
    const uint32_t XBIAS = h2u(1.0f, 0.0f);

    // tail-spread ordering: final-phase warps are wid 0-3 spread across ALL SMs
    const int o = wid * GRID + blockIdx.x;

    // ================= per-warp independent recurrences =================
    #pragma unroll 1
    for (int task = o; task < NTASKS; task += NWARPS) {
        const size_t growlo = (size_t)task * 16 + rlo;
        const float* xlo = x + growlo * XROW;
        const float* xhi = xlo + (size_t)8 * XROW;

        uint32_t hA[8][4];                 // h_t as ready-made A fragments (fp16x2)
        #pragma unroll
        for (int i = 0; i < 8; i++)
            #pragma unroll
            for (int r = 0; r < 4; r++) hA[i][r] = 0u;
        float cst[64];
        #pragma unroll
        for (int i = 0; i < 64; i++) cst[i] = 0.0f;

        // prefetch x for t=0
        float2 pa_lo = *(const float2*)(xlo + c0);
        float2 pa_hi = *(const float2*)(xhi + c0);
        float2 pb_lo = *(const float2*)(xlo + c0 + 8);
        float2 pb_hi = *(const float2*)(xhi + c0 + 8);
        float2 pc_lo = *(const float2*)(xlo + 16 + c0);
        float2 pc_hi = *(const float2*)(xhi + 16 + c0);
        float2 pd_lo = (xdmode == 0) ? *(const float2*)(xlo + 24 + c0) : make_float2(0, 0);
        float2 pd_hi = (xdmode == 0) ? *(const float2*)(xhi + 24 + c0) : make_float2(0, 0);

        #pragma unroll 1
        for (int t = 0; t < TSTEPS; t++) {
            const bool last = (t == TSTEPS - 1);

            // pack x A-fragments for this step
            uint32_t xf8[4], xf9[4];
            xf8[0] = f2u(pa_lo); xf8[1] = f2u(pa_hi);
            xf8[2] = f2u(pb_lo); xf8[3] = f2u(pb_hi);
            xf9[0] = f2u(pc_lo); xf9[1] = f2u(pc_hi);
            xf9[2] = (xdmode == 0) ? f2u(pd_lo) : ((xdmode == 1) ? XBIAS : 0u);
            xf9[3] = (xdmode == 0) ? f2u(pd_hi) : ((xdmode == 1) ? XBIAS : 0u);

            // prefetch x for t+1 (covers full MMA+epilogue latency)
            if (!last) {
                const float* ql = xlo + (size_t)(t + 1) * 28;
                const float* qh = xhi + (size_t)(t + 1) * 28;
                pa_lo = *(const float2*)(ql + c0);      pa_hi = *(const float2*)(qh + c0);
                pb_lo = *(const float2*)(ql + c0 + 8);  pb_hi = *(const float2*)(qh + c0 + 8);
                pc_lo = *(const float2*)(ql + 16 + c0); pc_hi = *(const float2*)(qh + 16 + c0);
                if (xdmode == 0) {
                    pd_lo = *(const float2*)(ql + 24 + c0);
                    pd_hi = *(const float2*)(qh + 24 + c0);
                }
            }

            uint32_t hN[8][4];

            #pragma unroll
            for (int ch = 0; ch < 8; ch++) {
                float acc[4][2][4];        // [gate][n8][reg]
                #pragma unroll
                for (int g = 0; g < 4; g++)
                    #pragma unroll
                    for (int n8 = 0; n8 < 2; n8++)
                        #pragma unroll
                        for (int r = 0; r < 4; r++) acc[g][n8][r] = 0.0f;

                #pragma unroll
                for (int ks = 0; ks < 10; ks++) {
                    const uint32_t* A = (ks < 8) ? hA[ks] : ((ks == 8) ? xf8 : xf9);
                    #pragma unroll
                    for (int g = 0; g < 4; g++) {
                        uint32_t b0, b1, b2, b3;
                        LDSM4(b0, b1, b2, b3,
                              bbase + (uint32_t)(((g << 7) + (ch << 4)) * (WSTR * 2)
                                                 + ks * 32));
                        MMA(acc[g][0], A[0], A[1], A[2], A[3], b0, b1);
                        MMA(acc[g][1], A[0], A[1], A[2], A[3], b2, b3);
                    }
                }

                // epilogue: 16 hidden units of this chunk (j = ch*16 + n8*8 + c0 + jc)
                #pragma unroll
                for (int n8 = 0; n8 < 2; n8++) {
                    #pragma unroll
                    for (int mi = 0; mi < 2; mi++) {
                        float hv0, hv1;
                        #pragma unroll
                        for (int jc = 0; jc < 2; jc++) {
                            const int ai = mi * 2 + jc;
                            float fs = fsig(acc[0][n8][ai]);
                            float is = fsig(acc[1][n8][ai]);
                            float ns = ftanh(acc[2][n8][ai]);
                            float os = fsig(acc[3][n8][ai]);
                            const int ci = (ch << 3) + (n8 << 2) + (mi << 1) + jc;
                            float cc = fmaf(cst[ci], fs, is * ns);
                            cst[ci] = cc;
                            float hh = os * ftanh(cc);
                            if (jc == 0) hv0 = hh; else hv1 = hh;
                        }
                        if (last) {
                            const int j = (ch << 4) + (n8 << 3) + c0;
                            *(float2*)(out + (growlo + mi * 8) * HID + j) =
                                make_float2(hv0, hv1);
                        } else {
                            hN[ch][(n8 << 1) + mi] = h2u(hv0, hv1);
                        }
                    }
                }
            }

            if (!last) {
                #pragma unroll
                for (int i = 0; i < 8; i++)
                    #pragma unroll
                    for (int r = 0; r < 4; r++) hA[i][r] = hN[i][r];
            }
        }
    }
}

extern "C" void kernel_launch(void* const* d_in, const int* in_sizes, int n_in,
                              void* d_out, int out_size) {
    (void)in_sizes; (void)n_in; (void)out_size;
    cudaFuncSetAttribute(lstm_kernel, cudaFuncAttributeMaxDynamicSharedMemorySize,
                         SMEM_TOTAL);
    lstm_kernel<<<GRID, TB, SMEM_TOTAL>>>(
        (const float*)d_in[0],
        (const float*)d_in[1], (const float*)d_in[2],
        (const float*)d_in[3], (const float*)d_in[4],
        (const float*)d_in[5], (const float*)d_in[6],
        (const float*)d_in[7], (const float*)d_in[8],
        (float*)d_out);
}